// round 1
// baseline (speedup 1.0000x reference)
#include <cuda_runtime.h>

#define BATCH 32
#define LC 512
#define LQ 64
#define DIM 1024

// ---------------- scratch (device globals; no allocation allowed) -----------
__device__ float g_s0[BATCH * LC];          // c @ proj_c
__device__ float g_s1[BATCH * LQ];          // q @ proj_q
__device__ float g_sim[BATCH * LC * LQ];    // similarity matrix (4 MiB)
__device__ float g_m[BATCH * LC];           // rowmax of sim over q
__device__ float g_q2c[BATCH * DIM];        // query-to-context vector

// ---------------- K-zero: clear q2c accumulator (graph replays) -------------
__global__ void k_zero_q2c() {
    int i = blockIdx.x * blockDim.x + threadIdx.x;
    if (i < BATCH * DIM) g_q2c[i] = 0.f;
}

// ---------------- K0: s0[b,c] = c . proj_c ; s1[b,j] = q . proj_q -----------
// one warp per row, float4 loads, warp shuffle reduce
__global__ void k_proj(const float* __restrict__ c, const float* __restrict__ q,
                       const float* __restrict__ pc, const float* __restrict__ pq) {
    int warp = (blockIdx.x * blockDim.x + threadIdx.x) >> 5;
    int lane = threadIdx.x & 31;
    const int NC = BATCH * LC;
    const int NT = NC + BATCH * LQ;
    if (warp >= NT) return;
    const float* src;
    const float* p;
    float* dst;
    if (warp < NC) { src = c + (size_t)warp * DIM; p = pc; dst = g_s0 + warp; }
    else { int r = warp - NC; src = q + (size_t)r * DIM; p = pq; dst = g_s1 + r; }
    float s = 0.f;
#pragma unroll
    for (int i = 0; i < 8; i++) {
        int k = (lane + i * 32) * 4;
        float4 v  = *(const float4*)(src + k);
        float4 pv = *(const float4*)(p + k);
        s += v.x * pv.x + v.y * pv.y + v.z * pv.z + v.w * pv.w;
    }
#pragma unroll
    for (int o = 16; o; o >>= 1) s += __shfl_xor_sync(0xffffffffu, s, o);
    if (lane == 0) *dst = s;
}

// ---------------- K1: sim[b,c,j] = s0 + s1 + (c*pcq) . q ; rowmax -----------
// 64x64 tile per block, K-tiled SGEMM, 256 threads, 4x4 microtile
#define KT 32
#define MT 64
#define SPAD 4
__global__ void k_sim(const float* __restrict__ c, const float* __restrict__ q,
                      const float* __restrict__ pcq) {
    __shared__ float As[KT][MT + SPAD];   // scaled c, [k][m]
    __shared__ float Bs[KT][MT + SPAD];   // q,        [k][n]
    int b = blockIdx.y, cm = blockIdx.x;
    int t = threadIdx.x;
    int tx = t & 15, ty = t >> 4;
    const float* cbase = c + ((size_t)b * LC + cm * MT) * DIM;
    const float* qbase = q + (size_t)b * LQ * DIM;
    float acc[4][4] = {};

    for (int k0 = 0; k0 < DIM; k0 += KT) {
#pragma unroll
        for (int i = 0; i < 2; i++) {
            int idx = t + i * 256;           // 0..511
            int r = idx >> 3;                // 0..63
            int kc = (idx & 7) << 2;         // 0,4,...,28
            float4 v  = *(const float4*)(cbase + (size_t)r * DIM + k0 + kc);
            float4 pv = *(const float4*)(pcq + k0 + kc);
            As[kc + 0][r] = v.x * pv.x;
            As[kc + 1][r] = v.y * pv.y;
            As[kc + 2][r] = v.z * pv.z;
            As[kc + 3][r] = v.w * pv.w;
            float4 u = *(const float4*)(qbase + (size_t)r * DIM + k0 + kc);
            Bs[kc + 0][r] = u.x;
            Bs[kc + 1][r] = u.y;
            Bs[kc + 2][r] = u.z;
            Bs[kc + 3][r] = u.w;
        }
        __syncthreads();
#pragma unroll
        for (int kk = 0; kk < KT; kk++) {
            float4 av = *(const float4*)&As[kk][ty << 2];
            float4 bv = *(const float4*)&Bs[kk][tx << 2];
            acc[0][0] = fmaf(av.x, bv.x, acc[0][0]);
            acc[0][1] = fmaf(av.x, bv.y, acc[0][1]);
            acc[0][2] = fmaf(av.x, bv.z, acc[0][2]);
            acc[0][3] = fmaf(av.x, bv.w, acc[0][3]);
            acc[1][0] = fmaf(av.y, bv.x, acc[1][0]);
            acc[1][1] = fmaf(av.y, bv.y, acc[1][1]);
            acc[1][2] = fmaf(av.y, bv.z, acc[1][2]);
            acc[1][3] = fmaf(av.y, bv.w, acc[1][3]);
            acc[2][0] = fmaf(av.z, bv.x, acc[2][0]);
            acc[2][1] = fmaf(av.z, bv.y, acc[2][1]);
            acc[2][2] = fmaf(av.z, bv.z, acc[2][2]);
            acc[2][3] = fmaf(av.z, bv.w, acc[2][3]);
            acc[3][0] = fmaf(av.w, bv.x, acc[3][0]);
            acc[3][1] = fmaf(av.w, bv.y, acc[3][1]);
            acc[3][2] = fmaf(av.w, bv.z, acc[3][2]);
            acc[3][3] = fmaf(av.w, bv.w, acc[3][3]);
        }
        __syncthreads();
    }

    // epilogue: add s0 + s1, write sim, reduce rowmax across the 16 tx lanes
    int row0 = cm * MT + (ty << 2);
    float s1v[4];
#pragma unroll
    for (int j = 0; j < 4; j++) s1v[j] = g_s1[b * LQ + (tx << 2) + j];
#pragma unroll
    for (int i = 0; i < 4; i++) {
        int row = row0 + i;
        float s0v = g_s0[b * LC + row];
        float4 o;
        o.x = acc[i][0] + s0v + s1v[0];
        o.y = acc[i][1] + s0v + s1v[1];
        o.z = acc[i][2] + s0v + s1v[2];
        o.w = acc[i][3] + s0v + s1v[3];
        float rm = fmaxf(fmaxf(o.x, o.y), fmaxf(o.z, o.w));
#pragma unroll
        for (int off = 1; off < 16; off <<= 1)
            rm = fmaxf(rm, __shfl_xor_sync(0xffffffffu, rm, off));
        *(float4*)&g_sim[((size_t)b * LC + row) * LQ + (tx << 2)] = o;
        if (tx == 0) g_m[b * LC + row] = rm;
    }
}

// ---------------- K2: q2c[b,:] = softmax_c(m) @ c[b] ------------------------
// grid (8, B): each block handles 64 c-rows, atomicAdd partials into g_q2c
__global__ void k_q2c(const float* __restrict__ c) {
    __shared__ float wm[LC];
    __shared__ float red[256];
    int b = blockIdx.y, cb = blockIdx.x;
    int t = threadIdx.x;
    float v0 = g_m[b * LC + t];
    float v1 = g_m[b * LC + 256 + t];
    red[t] = fmaxf(v0, v1);
    __syncthreads();
#pragma unroll
    for (int s = 128; s > 0; s >>= 1) {
        if (t < s) red[t] = fmaxf(red[t], red[t + s]);
        __syncthreads();
    }
    float mx = red[0];
    __syncthreads();
    float e0 = expf(v0 - mx), e1 = expf(v1 - mx);
    wm[t] = e0;
    wm[t + 256] = e1;
    red[t] = e0 + e1;
    __syncthreads();
#pragma unroll
    for (int s = 128; s > 0; s >>= 1) {
        if (t < s) red[t] += red[t + s];
        __syncthreads();
    }
    float inv = 1.f / red[0];
    __syncthreads();

    float4 acc = {0.f, 0.f, 0.f, 0.f};
    const float* cb0 = c + ((size_t)b * LC + cb * 64) * DIM + (t << 2);
#pragma unroll 4
    for (int cr = 0; cr < 64; cr++) {
        float w = wm[cb * 64 + cr] * inv;
        float4 cv = *(const float4*)(cb0 + (size_t)cr * DIM);
        acc.x = fmaf(w, cv.x, acc.x);
        acc.y = fmaf(w, cv.y, acc.y);
        acc.z = fmaf(w, cv.z, acc.z);
        acc.w = fmaf(w, cv.w, acc.w);
    }
    float* dst = g_q2c + b * DIM + (t << 2);
    atomicAdd(dst + 0, acc.x);
    atomicAdd(dst + 1, acc.y);
    atomicAdd(dst + 2, acc.z);
    atomicAdd(dst + 3, acc.w);
}

// ---------------- K3: softmax rows, c2q = a @ q, fused output write ---------
// grid (16, B): 32 c-rows per block, d processed in 128-wide chunks
#define RT 32
#define DC 128
__global__ void k_out(const float* __restrict__ c, const float* __restrict__ q,
                      float* __restrict__ out) {
    __shared__ float a_s[RT][LQ];        // softmax(sim) rows
    __shared__ float q_s[LQ][DC];        // q chunk
    int b = blockIdx.y, ct = blockIdx.x;
    int t = threadIdx.x;
    int warp = t >> 5, lane = t & 31;

    // row softmax using stored rowmax
#pragma unroll
    for (int i = 0; i < 4; i++) {
        int r = warp * 4 + i;
        int row = ct * RT + r;
        size_t sbase = ((size_t)b * LC + row) * LQ;
        float m = g_m[b * LC + row];
        float v0 = expf(g_sim[sbase + lane] - m);
        float v1 = expf(g_sim[sbase + lane + 32] - m);
        float s = v0 + v1;
#pragma unroll
        for (int o = 16; o; o >>= 1) s += __shfl_xor_sync(0xffffffffu, s, o);
        float inv = 1.f / s;
        a_s[r][lane] = v0 * inv;
        a_s[r][lane + 32] = v1 * inv;
    }
    __syncthreads();

    int col4 = t & 31;   // owns 4 consecutive d
    int r0 = t >> 5;     // rows r0, r0+8, r0+16, r0+24
    const float* qb = q + (size_t)b * LQ * DIM;

    for (int dc = 0; dc < DIM; dc += DC) {
#pragma unroll
        for (int i = 0; i < 8; i++) {
            int idx = t + i * 256;
            int qr = idx >> 5;
            int qc = (idx & 31) << 2;
            *(float4*)&q_s[qr][qc] = *(const float4*)(qb + (size_t)qr * DIM + dc + qc);
        }
        __syncthreads();

        float4 acc[4] = {};
#pragma unroll 4
        for (int qq = 0; qq < LQ; qq++) {
            float4 qv = *(const float4*)&q_s[qq][col4 << 2];
#pragma unroll
            for (int k = 0; k < 4; k++) {
                float a = a_s[r0 + 8 * k][qq];
                acc[k].x = fmaf(a, qv.x, acc[k].x);
                acc[k].y = fmaf(a, qv.y, acc[k].y);
                acc[k].z = fmaf(a, qv.z, acc[k].z);
                acc[k].w = fmaf(a, qv.w, acc[k].w);
            }
        }

        int d = dc + (col4 << 2);
        float4 qc4 = *(const float4*)(g_q2c + b * DIM + d);
#pragma unroll
        for (int k = 0; k < 4; k++) {
            int row = ct * RT + r0 + 8 * k;
            float4 cv = *(const float4*)(c + ((size_t)b * LC + row) * DIM + d);
            float* ob = out + ((size_t)b * LC + row) * (4 * DIM) + d;
            *(float4*)(ob) = cv;
            *(float4*)(ob + DIM) = acc[k];
            float4 t2 = {cv.x * qc4.x, cv.y * qc4.y, cv.z * qc4.z, cv.w * qc4.w};
            *(float4*)(ob + 2 * DIM) = t2;
            float4 t3 = {cv.x * acc[k].x, cv.y * acc[k].y, cv.z * acc[k].z, cv.w * acc[k].w};
            *(float4*)(ob + 3 * DIM) = t3;
        }
        __syncthreads();
    }
}

// ---------------- launch -----------------------------------------------------
extern "C" void kernel_launch(void* const* d_in, const int* in_sizes, int n_in,
                              void* d_out, int out_size) {
    const float* c   = (const float*)d_in[0];
    const float* q   = (const float*)d_in[1];
    const float* pc  = (const float*)d_in[2];
    const float* pq  = (const float*)d_in[3];
    const float* pcq = (const float*)d_in[4];
    float* out = (float*)d_out;
    (void)in_sizes; (void)n_in; (void)out_size;

    k_zero_q2c<<<(BATCH * DIM + 255) / 256, 256>>>();
    k_proj<<<(BATCH * (LC + LQ) * 32 + 255) / 256, 256>>>(c, q, pc, pq);
    k_sim<<<dim3(LC / MT, BATCH), 256>>>(c, q, pcq);
    k_q2c<<<dim3(LC / 64, BATCH), 256>>>(c);
    k_out<<<dim3(LC / RT, BATCH), 256>>>(c, q, out);
}

// round 2
// speedup vs baseline: 1.4556x; 1.4556x over previous
#include <cuda_runtime.h>

#define BATCH 32
#define LC 512
#define LQ 64
#define DIM 1024

// ---------------- scratch (device globals; no allocation allowed) -----------
__device__ float g_s0[BATCH * LC];          // c @ proj_c
__device__ float g_s1[BATCH * LQ];          // q @ proj_q
__device__ float g_sim[BATCH * LC * LQ];    // similarity matrix (4 MiB)
__device__ float g_m[BATCH * LC];           // rowmax of sim over q
__device__ float g_q2c[BATCH * DIM];        // query-to-context vector

// ---------------- K-zero: clear q2c accumulator (graph replays) -------------
__global__ void k_zero_q2c() {
    int i = blockIdx.x * blockDim.x + threadIdx.x;
    if (i < BATCH * DIM) g_q2c[i] = 0.f;
}

// ---------------- K0: s0[b,c] = c . proj_c ; s1[b,j] = q . proj_q -----------
// one warp per row, float4 loads, warp shuffle reduce
__global__ void k_proj(const float* __restrict__ c, const float* __restrict__ q,
                       const float* __restrict__ pc, const float* __restrict__ pq) {
    int warp = (blockIdx.x * blockDim.x + threadIdx.x) >> 5;
    int lane = threadIdx.x & 31;
    const int NC = BATCH * LC;
    const int NT = NC + BATCH * LQ;
    if (warp >= NT) return;
    const float* src;
    const float* p;
    float* dst;
    if (warp < NC) { src = c + (size_t)warp * DIM; p = pc; dst = g_s0 + warp; }
    else { int r = warp - NC; src = q + (size_t)r * DIM; p = pq; dst = g_s1 + r; }
    float s = 0.f;
#pragma unroll
    for (int i = 0; i < 8; i++) {
        int k = (lane + i * 32) * 4;
        float4 v  = *(const float4*)(src + k);
        float4 pv = *(const float4*)(p + k);
        s += v.x * pv.x + v.y * pv.y + v.z * pv.z + v.w * pv.w;
    }
#pragma unroll
    for (int o = 16; o; o >>= 1) s += __shfl_xor_sync(0xffffffffu, s, o);
    if (lane == 0) *dst = s;
}

// ---------------- K1: sim[b,c,j] = s0 + s1 + (c*pcq) . q ; rowmax -----------
// 64x64 tile per block, K-tiled SGEMM, 256 threads, 4x4 microtile
#define KT 32
#define MT 64
#define SPAD 4
__global__ void k_sim(const float* __restrict__ c, const float* __restrict__ q,
                      const float* __restrict__ pcq) {
    __shared__ float As[KT][MT + SPAD];   // scaled c, [k][m]
    __shared__ float Bs[KT][MT + SPAD];   // q,        [k][n]
    int b = blockIdx.y, cm = blockIdx.x;
    int t = threadIdx.x;
    int tx = t & 15, ty = t >> 4;
    const float* cbase = c + ((size_t)b * LC + cm * MT) * DIM;
    const float* qbase = q + (size_t)b * LQ * DIM;
    float acc[4][4] = {};

    for (int k0 = 0; k0 < DIM; k0 += KT) {
#pragma unroll
        for (int i = 0; i < 2; i++) {
            int idx = t + i * 256;           // 0..511
            int r = idx >> 3;                // 0..63
            int kc = (idx & 7) << 2;         // 0,4,...,28
            float4 v  = *(const float4*)(cbase + (size_t)r * DIM + k0 + kc);
            float4 pv = *(const float4*)(pcq + k0 + kc);
            As[kc + 0][r] = v.x * pv.x;
            As[kc + 1][r] = v.y * pv.y;
            As[kc + 2][r] = v.z * pv.z;
            As[kc + 3][r] = v.w * pv.w;
            float4 u = *(const float4*)(qbase + (size_t)r * DIM + k0 + kc);
            Bs[kc + 0][r] = u.x;
            Bs[kc + 1][r] = u.y;
            Bs[kc + 2][r] = u.z;
            Bs[kc + 3][r] = u.w;
        }
        __syncthreads();
#pragma unroll
        for (int kk = 0; kk < KT; kk++) {
            float4 av = *(const float4*)&As[kk][ty << 2];
            float4 bv = *(const float4*)&Bs[kk][tx << 2];
            acc[0][0] = fmaf(av.x, bv.x, acc[0][0]);
            acc[0][1] = fmaf(av.x, bv.y, acc[0][1]);
            acc[0][2] = fmaf(av.x, bv.z, acc[0][2]);
            acc[0][3] = fmaf(av.x, bv.w, acc[0][3]);
            acc[1][0] = fmaf(av.y, bv.x, acc[1][0]);
            acc[1][1] = fmaf(av.y, bv.y, acc[1][1]);
            acc[1][2] = fmaf(av.y, bv.z, acc[1][2]);
            acc[1][3] = fmaf(av.y, bv.w, acc[1][3]);
            acc[2][0] = fmaf(av.z, bv.x, acc[2][0]);
            acc[2][1] = fmaf(av.z, bv.y, acc[2][1]);
            acc[2][2] = fmaf(av.z, bv.z, acc[2][2]);
            acc[2][3] = fmaf(av.z, bv.w, acc[2][3]);
            acc[3][0] = fmaf(av.w, bv.x, acc[3][0]);
            acc[3][1] = fmaf(av.w, bv.y, acc[3][1]);
            acc[3][2] = fmaf(av.w, bv.z, acc[3][2]);
            acc[3][3] = fmaf(av.w, bv.w, acc[3][3]);
        }
        __syncthreads();
    }

    // epilogue: add s0 + s1, write sim, reduce rowmax across the 16 tx lanes
    int row0 = cm * MT + (ty << 2);
    float s1v[4];
#pragma unroll
    for (int j = 0; j < 4; j++) s1v[j] = g_s1[b * LQ + (tx << 2) + j];
#pragma unroll
    for (int i = 0; i < 4; i++) {
        int row = row0 + i;
        float s0v = g_s0[b * LC + row];
        float4 o;
        o.x = acc[i][0] + s0v + s1v[0];
        o.y = acc[i][1] + s0v + s1v[1];
        o.z = acc[i][2] + s0v + s1v[2];
        o.w = acc[i][3] + s0v + s1v[3];
        float rm = fmaxf(fmaxf(o.x, o.y), fmaxf(o.z, o.w));
#pragma unroll
        for (int off = 1; off < 16; off <<= 1)
            rm = fmaxf(rm, __shfl_xor_sync(0xffffffffu, rm, off));
        *(float4*)&g_sim[((size_t)b * LC + row) * LQ + (tx << 2)] = o;
        if (tx == 0) g_m[b * LC + row] = rm;
    }
}

// ---------------- K2: q2c[b,:] = softmax_c(m) @ c[b] ------------------------
// grid (8, B): each block handles 64 c-rows, atomicAdd partials into g_q2c
__global__ void k_q2c(const float* __restrict__ c) {
    __shared__ float wm[LC];
    __shared__ float red[256];
    int b = blockIdx.y, cb = blockIdx.x;
    int t = threadIdx.x;
    float v0 = g_m[b * LC + t];
    float v1 = g_m[b * LC + 256 + t];
    red[t] = fmaxf(v0, v1);
    __syncthreads();
#pragma unroll
    for (int s = 128; s > 0; s >>= 1) {
        if (t < s) red[t] = fmaxf(red[t], red[t + s]);
        __syncthreads();
    }
    float mx = red[0];
    __syncthreads();
    float e0 = expf(v0 - mx), e1 = expf(v1 - mx);
    wm[t] = e0;
    wm[t + 256] = e1;
    red[t] = e0 + e1;
    __syncthreads();
#pragma unroll
    for (int s = 128; s > 0; s >>= 1) {
        if (t < s) red[t] += red[t + s];
        __syncthreads();
    }
    float inv = 1.f / red[0];
    __syncthreads();

    float4 acc = {0.f, 0.f, 0.f, 0.f};
    const float* cb0 = c + ((size_t)b * LC + cb * 64) * DIM + (t << 2);
#pragma unroll 4
    for (int cr = 0; cr < 64; cr++) {
        float w = wm[cb * 64 + cr] * inv;
        float4 cv = *(const float4*)(cb0 + (size_t)cr * DIM);
        acc.x = fmaf(w, cv.x, acc.x);
        acc.y = fmaf(w, cv.y, acc.y);
        acc.z = fmaf(w, cv.z, acc.z);
        acc.w = fmaf(w, cv.w, acc.w);
    }
    float* dst = g_q2c + b * DIM + (t << 2);
    atomicAdd(dst + 0, acc.x);
    atomicAdd(dst + 1, acc.y);
    atomicAdd(dst + 2, acc.z);
    atomicAdd(dst + 3, acc.w);
}

// ---------------- K3: softmax rows, c2q = a @ q, fused output write ---------
// grid (16, B): 32 c-rows per block, d processed in 128-wide chunks
#define RT 32
#define DC 128
__global__ void k_out(const float* __restrict__ c, const float* __restrict__ q,
                      float* __restrict__ out) {
    __shared__ float a_s[RT][LQ];        // softmax(sim) rows
    __shared__ float q_s[LQ][DC];        // q chunk
    int b = blockIdx.y, ct = blockIdx.x;
    int t = threadIdx.x;
    int warp = t >> 5, lane = t & 31;

    // row softmax using stored rowmax
#pragma unroll
    for (int i = 0; i < 4; i++) {
        int r = warp * 4 + i;
        int row = ct * RT + r;
        size_t sbase = ((size_t)b * LC + row) * LQ;
        float m = g_m[b * LC + row];
        float v0 = expf(g_sim[sbase + lane] - m);
        float v1 = expf(g_sim[sbase + lane + 32] - m);
        float s = v0 + v1;
#pragma unroll
        for (int o = 16; o; o >>= 1) s += __shfl_xor_sync(0xffffffffu, s, o);
        float inv = 1.f / s;
        a_s[r][lane] = v0 * inv;
        a_s[r][lane + 32] = v1 * inv;
    }
    __syncthreads();

    int col4 = t & 31;   // owns 4 consecutive d
    int r0 = t >> 5;     // rows r0, r0+8, r0+16, r0+24
    const float* qb = q + (size_t)b * LQ * DIM;

    for (int dc = 0; dc < DIM; dc += DC) {
#pragma unroll
        for (int i = 0; i < 8; i++) {
            int idx = t + i * 256;
            int qr = idx >> 5;
            int qc = (idx & 31) << 2;
            *(float4*)&q_s[qr][qc] = *(const float4*)(qb + (size_t)qr * DIM + dc + qc);
        }
        __syncthreads();

        float4 acc[4] = {};
#pragma unroll 4
        for (int qq = 0; qq < LQ; qq++) {
            float4 qv = *(const float4*)&q_s[qq][col4 << 2];
#pragma unroll
            for (int k = 0; k < 4; k++) {
                float a = a_s[r0 + 8 * k][qq];
                acc[k].x = fmaf(a, qv.x, acc[k].x);
                acc[k].y = fmaf(a, qv.y, acc[k].y);
                acc[k].z = fmaf(a, qv.z, acc[k].z);
                acc[k].w = fmaf(a, qv.w, acc[k].w);
            }
        }

        int d = dc + (col4 << 2);
        float4 qc4 = *(const float4*)(g_q2c + b * DIM + d);
#pragma unroll
        for (int k = 0; k < 4; k++) {
            int row = ct * RT + r0 + 8 * k;
            float4 cv = *(const float4*)(c + ((size_t)b * LC + row) * DIM + d);
            float* ob = out + ((size_t)b * LC + row) * (4 * DIM) + d;
            *(float4*)(ob) = cv;
            *(float4*)(ob + DIM) = acc[k];
            float4 t2 = {cv.x * qc4.x, cv.y * qc4.y, cv.z * qc4.z, cv.w * qc4.w};
            *(float4*)(ob + 2 * DIM) = t2;
            float4 t3 = {cv.x * acc[k].x, cv.y * acc[k].y, cv.z * acc[k].z, cv.w * acc[k].w};
            *(float4*)(ob + 3 * DIM) = t3;
        }
        __syncthreads();
    }
}

// ---------------- launch -----------------------------------------------------
extern "C" void kernel_launch(void* const* d_in, const int* in_sizes, int n_in,
                              void* d_out, int out_size) {
    const float* c   = (const float*)d_in[0];
    const float* q   = (const float*)d_in[1];
    const float* pc  = (const float*)d_in[2];
    const float* pq  = (const float*)d_in[3];
    const float* pcq = (const float*)d_in[4];
    float* out = (float*)d_out;
    (void)in_sizes; (void)n_in; (void)out_size;

    k_zero_q2c<<<(BATCH * DIM + 255) / 256, 256>>>();
    k_proj<<<(BATCH * (LC + LQ) * 32 + 255) / 256, 256>>>(c, q, pc, pq);
    k_sim<<<dim3(LC / MT, BATCH), 256>>>(c, q, pcq);
    k_q2c<<<dim3(LC / 64, BATCH), 256>>>(c);
    k_out<<<dim3(LC / RT, BATCH), 256>>>(c, q, out);
}

// round 3
// speedup vs baseline: 1.5803x; 1.0857x over previous
#include <cuda_runtime.h>

#define BATCH 32
#define LC 512
#define LQ 64
#define DIM 1024

typedef unsigned long long u64;

__device__ __forceinline__ u64 ffma2(u64 a, u64 b, u64 c) {
    u64 d;
    asm("fma.rn.f32x2 %0, %1, %2, %3;" : "=l"(d) : "l"(a), "l"(b), "l"(c));
    return d;
}
__device__ __forceinline__ u64 pack2(float x, float y) {
    u64 d;
    asm("mov.b64 %0, {%1, %2};" : "=l"(d) : "f"(x), "f"(y));
    return d;
}
__device__ __forceinline__ float2 unpack2(u64 v) {
    float2 r;
    asm("mov.b64 {%0, %1}, %2;" : "=f"(r.x), "=f"(r.y) : "l"(v));
    return r;
}
__device__ __forceinline__ float pairsum(u64 v) {
    float2 r = unpack2(v);
    return r.x + r.y;
}

// ---------------- scratch -----------------------------------------------------
__device__ float g_sim[BATCH * LC * LQ];    // similarity matrix (4 MiB)
__device__ float g_m[BATCH * LC];           // rowmax of sim over q
__device__ float g_q2c[BATCH * DIM];        // query-to-context vector

// ---------------- K1: fused proj + sim GEMM (f32x2, K-paired) ---------------
// 64x64 tile per block, 256 threads, 4x4 microtile with stride-16 ownership.
// Also: computes s0 = c.pc and s1 = q.pq from the same global loads, and
// block x==0 zeroes g_q2c for the downstream atomic accumulation.
#define KT 32
#define MT 64
#define AW (2 * MT + 4)   // pair-interleaved row width (floats)
#define BW (2 * LQ + 4)
__global__ void k_sim(const float* __restrict__ c, const float* __restrict__ q,
                      const float* __restrict__ pc, const float* __restrict__ pq,
                      const float* __restrict__ pcq) {
    __shared__ __align__(16) float As2[KT / 2][AW];  // (c*pcq), pairs over k
    __shared__ __align__(16) float Bs2[KT / 2][BW];  // q, pairs over k
    __shared__ float s0s[MT];
    __shared__ float s1s[LQ];

    int b = blockIdx.y, cm = blockIdx.x;
    int t = threadIdx.x;
    int tx = t & 15, ty = t >> 4;

    if (cm == 0) {   // zero q2c accumulator (k_q2c runs after this kernel)
#pragma unroll
        for (int i = 0; i < DIM / 256; i++) g_q2c[b * DIM + t + i * 256] = 0.f;
    }

    const float* cbase = c + ((size_t)b * LC + cm * MT) * DIM;
    const float* qbase = q + (size_t)b * LQ * DIM;

    u64 acc[4][4];
#pragma unroll
    for (int i = 0; i < 4; i++)
#pragma unroll
        for (int j = 0; j < 4; j++) acc[i][j] = 0ull;

    int r_ld = t >> 3;              // 0..31 (also row+32)
    int kc = (t & 7) << 2;          // k offset within tile: 0..28
    int kc2 = (t & 7) << 1;         // pair-row in As2/Bs2

    float sc[2] = {0.f, 0.f};       // partial c.pc for rows r_ld, r_ld+32
    float sq[2] = {0.f, 0.f};       // partial q.pq

    for (int k0 = 0; k0 < DIM; k0 += KT) {
        float4 pv  = *(const float4*)(pcq + k0 + kc);
        float4 pcv = *(const float4*)(pc + k0 + kc);
        float4 pqv = *(const float4*)(pq + k0 + kc);
#pragma unroll
        for (int ii = 0; ii < 2; ii++) {
            int r = r_ld + ii * 32;
            float4 v = *(const float4*)(cbase + (size_t)r * DIM + k0 + kc);
            sc[ii] += v.x * pcv.x + v.y * pcv.y + v.z * pcv.z + v.w * pcv.w;
            *(float2*)&As2[kc2][2 * r]     = make_float2(v.x * pv.x, v.y * pv.y);
            *(float2*)&As2[kc2 + 1][2 * r] = make_float2(v.z * pv.z, v.w * pv.w);
            float4 u = *(const float4*)(qbase + (size_t)r * DIM + k0 + kc);
            sq[ii] += u.x * pqv.x + u.y * pqv.y + u.z * pqv.z + u.w * pqv.w;
            *(float2*)&Bs2[kc2][2 * r]     = make_float2(u.x, u.y);
            *(float2*)&Bs2[kc2 + 1][2 * r] = make_float2(u.z, u.w);
        }
        __syncthreads();
#pragma unroll
        for (int kk2 = 0; kk2 < KT / 2; kk2++) {
            u64 am[4], bn[4];
#pragma unroll
            for (int i = 0; i < 4; i++)
                am[i] = *(const u64*)&As2[kk2][2 * (ty + 16 * i)];
#pragma unroll
            for (int j = 0; j < 4; j++)
                bn[j] = *(const u64*)&Bs2[kk2][2 * (tx + 16 * j)];
#pragma unroll
            for (int i = 0; i < 4; i++)
#pragma unroll
                for (int j = 0; j < 4; j++)
                    acc[i][j] = ffma2(am[i], bn[j], acc[i][j]);
        }
        __syncthreads();
    }

    // reduce s0/s1 partials across the 8 lanes sharing a row
#pragma unroll
    for (int o = 4; o; o >>= 1) {
        sc[0] += __shfl_xor_sync(0xffffffffu, sc[0], o);
        sc[1] += __shfl_xor_sync(0xffffffffu, sc[1], o);
        sq[0] += __shfl_xor_sync(0xffffffffu, sq[0], o);
        sq[1] += __shfl_xor_sync(0xffffffffu, sq[1], o);
    }
    if ((t & 7) == 0) {
        s0s[r_ld] = sc[0]; s0s[r_ld + 32] = sc[1];
        s1s[r_ld] = sq[0]; s1s[r_ld + 32] = sq[1];
    }
    __syncthreads();

    // epilogue: add s0+s1, rowmax over the 16 tx lanes, write sim + m
    float s1v[4];
#pragma unroll
    for (int j = 0; j < 4; j++) s1v[j] = s1s[tx + 16 * j];
#pragma unroll
    for (int i = 0; i < 4; i++) {
        int mrow = ty + 16 * i;
        int row = cm * MT + mrow;
        float s0v = s0s[mrow];
        float vals[4];
        float rm = -3.4e38f;
#pragma unroll
        for (int j = 0; j < 4; j++) {
            vals[j] = pairsum(acc[i][j]) + s0v + s1v[j];
            rm = fmaxf(rm, vals[j]);
        }
#pragma unroll
        for (int o = 8; o; o >>= 1) rm = fmaxf(rm, __shfl_xor_sync(0xffffffffu, rm, o));
        size_t sbase = ((size_t)b * LC + row) * LQ;
#pragma unroll
        for (int j = 0; j < 4; j++) g_sim[sbase + tx + 16 * j] = vals[j];
        if (tx == 0) g_m[b * LC + row] = rm;
    }
}

// ---------------- K2: q2c[b,:] = softmax_c(m) @ c[b] ------------------------
// grid (16, B): 32 c-rows per block, unroll-8 for MLP; atomicAdd partials
__global__ void k_q2c(const float* __restrict__ c) {
    __shared__ float wm[LC];
    __shared__ float red[256];
    int b = blockIdx.y, cb = blockIdx.x;
    int t = threadIdx.x;
    float v0 = g_m[b * LC + t];
    float v1 = g_m[b * LC + 256 + t];
    red[t] = fmaxf(v0, v1);
    __syncthreads();
#pragma unroll
    for (int s = 128; s > 0; s >>= 1) {
        if (t < s) red[t] = fmaxf(red[t], red[t + s]);
        __syncthreads();
    }
    float mx = red[0];
    __syncthreads();
    float e0 = expf(v0 - mx), e1 = expf(v1 - mx);
    wm[t] = e0;
    wm[t + 256] = e1;
    red[t] = e0 + e1;
    __syncthreads();
#pragma unroll
    for (int s = 128; s > 0; s >>= 1) {
        if (t < s) red[t] += red[t + s];
        __syncthreads();
    }
    float inv = 1.f / red[0];
    __syncthreads();

    float4 acc = {0.f, 0.f, 0.f, 0.f};
    const float* cb0 = c + ((size_t)b * LC + cb * 32) * DIM + (t << 2);
#pragma unroll 8
    for (int cr = 0; cr < 32; cr++) {
        float w = wm[cb * 32 + cr] * inv;
        float4 cv = *(const float4*)(cb0 + (size_t)cr * DIM);
        acc.x = fmaf(w, cv.x, acc.x);
        acc.y = fmaf(w, cv.y, acc.y);
        acc.z = fmaf(w, cv.z, acc.z);
        acc.w = fmaf(w, cv.w, acc.w);
    }
    float* dst = g_q2c + b * DIM + (t << 2);
    atomicAdd(dst + 0, acc.x);
    atomicAdd(dst + 1, acc.y);
    atomicAdd(dst + 2, acc.z);
    atomicAdd(dst + 3, acc.w);
}

// ---------------- K3: softmax rows, c2q = a @ q (f32x2), fused output -------
// grid (8, B): 64 c-rows per block; each warp owns 8 rows, lanes own 4 d.
#define RT 64
#define DC 128
__global__ void k_out(const float* __restrict__ c, const float* __restrict__ q,
                      float* __restrict__ out) {
    __shared__ __align__(16) float a_sT[LQ][RT];  // [qq][row] probs (16 KB)
    __shared__ __align__(16) float q_s[LQ][DC];   // q chunk (32 KB)
    int b = blockIdx.y, ct = blockIdx.x;
    int t = threadIdx.x;
    int warp = t >> 5, lane = t & 31;

    // row softmax using stored rowmax; store transposed for contiguous a-reads
#pragma unroll
    for (int i = 0; i < 8; i++) {
        int r = warp * 8 + i;
        int row = ct * RT + r;
        size_t sbase = ((size_t)b * LC + row) * LQ;
        float m = g_m[b * LC + row];
        float v0 = expf(g_sim[sbase + lane] - m);
        float v1 = expf(g_sim[sbase + lane + 32] - m);
        float s = v0 + v1;
#pragma unroll
        for (int o = 16; o; o >>= 1) s += __shfl_xor_sync(0xffffffffu, s, o);
        float inv = 1.f / s;
        a_sT[lane][r] = v0 * inv;
        a_sT[lane + 32][r] = v1 * inv;
    }
    __syncthreads();

    int col4 = t & 31;   // owns d = dc + col4*4 .. +3
    int r0 = warp;       // owns rows r0*8 .. r0*8+7
    const float* qb = q + (size_t)b * LQ * DIM;

    for (int dc = 0; dc < DIM; dc += DC) {
#pragma unroll
        for (int i = 0; i < 8; i++) {
            int idx = t + i * 256;
            int qr = idx >> 5;
            int qc = (idx & 31) << 2;
            *(float4*)&q_s[qr][qc] = *(const float4*)(qb + (size_t)qr * DIM + dc + qc);
        }
        __syncthreads();

        u64 acc2[8][2];
#pragma unroll
        for (int k = 0; k < 8; k++) { acc2[k][0] = 0ull; acc2[k][1] = 0ull; }

#pragma unroll 8
        for (int qq = 0; qq < LQ; qq++) {
            ulonglong2 qv = *(const ulonglong2*)&q_s[qq][col4 << 2];
            float4 a03 = *(const float4*)&a_sT[qq][r0 * 8];
            float4 a47 = *(const float4*)&a_sT[qq][r0 * 8 + 4];
            u64 ap[8];
            ap[0] = pack2(a03.x, a03.x);
            ap[1] = pack2(a03.y, a03.y);
            ap[2] = pack2(a03.z, a03.z);
            ap[3] = pack2(a03.w, a03.w);
            ap[4] = pack2(a47.x, a47.x);
            ap[5] = pack2(a47.y, a47.y);
            ap[6] = pack2(a47.z, a47.z);
            ap[7] = pack2(a47.w, a47.w);
#pragma unroll
            for (int k = 0; k < 8; k++) {
                acc2[k][0] = ffma2(ap[k], qv.x, acc2[k][0]);
                acc2[k][1] = ffma2(ap[k], qv.y, acc2[k][1]);
            }
        }
        __syncthreads();

        int d = dc + (col4 << 2);
        float4 qc4 = *(const float4*)(g_q2c + b * DIM + d);
#pragma unroll
        for (int k = 0; k < 8; k++) {
            float2 lo = unpack2(acc2[k][0]);
            float2 hi = unpack2(acc2[k][1]);
            float4 a4 = {lo.x, lo.y, hi.x, hi.y};
            int row = ct * RT + r0 * 8 + k;
            float4 cv = *(const float4*)(c + ((size_t)b * LC + row) * DIM + d);
            float* ob = out + ((size_t)b * LC + row) * (4 * DIM) + d;
            *(float4*)(ob) = cv;
            *(float4*)(ob + DIM) = a4;
            float4 t2 = {cv.x * qc4.x, cv.y * qc4.y, cv.z * qc4.z, cv.w * qc4.w};
            *(float4*)(ob + 2 * DIM) = t2;
            float4 t3 = {cv.x * a4.x, cv.y * a4.y, cv.z * a4.z, cv.w * a4.w};
            *(float4*)(ob + 3 * DIM) = t3;
        }
    }
}

// ---------------- launch -----------------------------------------------------
extern "C" void kernel_launch(void* const* d_in, const int* in_sizes, int n_in,
                              void* d_out, int out_size) {
    const float* c   = (const float*)d_in[0];
    const float* q   = (const float*)d_in[1];
    const float* pc  = (const float*)d_in[2];
    const float* pq  = (const float*)d_in[3];
    const float* pcq = (const float*)d_in[4];
    float* out = (float*)d_out;
    (void)in_sizes; (void)n_in; (void)out_size;

    k_sim<<<dim3(LC / MT, BATCH), 256>>>(c, q, pc, pq, pcq);
    k_q2c<<<dim3(16, BATCH), 256>>>(c);
    k_out<<<dim3(LC / RT, BATCH), 256>>>(c, q, out);
}

// round 4
// speedup vs baseline: 1.7553x; 1.1107x over previous
#include <cuda_runtime.h>

#define BATCH 32
#define LC 512
#define LQ 64
#define DIM 1024

typedef unsigned long long u64;

__device__ __forceinline__ u64 ffma2(u64 a, u64 b, u64 c) {
    u64 d;
    asm("fma.rn.f32x2 %0, %1, %2, %3;" : "=l"(d) : "l"(a), "l"(b), "l"(c));
    return d;
}
__device__ __forceinline__ u64 pack2(float x, float y) {
    u64 d;
    asm("mov.b64 %0, {%1, %2};" : "=l"(d) : "f"(x), "f"(y));
    return d;
}
__device__ __forceinline__ float2 unpack2(u64 v) {
    float2 r;
    asm("mov.b64 {%0, %1}, %2;" : "=f"(r.x), "=f"(r.y) : "l"(v));
    return r;
}
__device__ __forceinline__ float pairsum(u64 v) {
    float2 r = unpack2(v);
    return r.x + r.y;
}
__device__ __forceinline__ void cp16(unsigned saddr, const void* gaddr) {
    asm volatile("cp.async.cg.shared.global [%0], [%1], 16;"
                 :: "r"(saddr), "l"(gaddr) : "memory");
}
#define CP_COMMIT() asm volatile("cp.async.commit_group;" ::: "memory")
#define CP_WAIT1()  asm volatile("cp.async.wait_group 1;" ::: "memory")

// ---------------- scratch -----------------------------------------------------
__device__ float g_s0[BATCH * LC];          // c @ proj_c
__device__ float g_s1[BATCH * LQ];          // q @ proj_q
__device__ float g_qs[BATCH * LQ * DIM];    // q * proj_cq (8 MiB)
__device__ float g_sim[BATCH * LC * LQ];    // similarity matrix (4 MiB)
__device__ float g_m[BATCH * LC];           // rowmax of sim over q
__device__ float g_q2c[BATCH * DIM];        // query-to-context vector

// ---------------- K0: projections + scaled q + zero q2c ---------------------
// one warp per row (16384 c-rows then 2048 q-rows)
__global__ void k_pre(const float* __restrict__ c, const float* __restrict__ q,
                      const float* __restrict__ pc, const float* __restrict__ pq,
                      const float* __restrict__ pcq) {
    int gtid = blockIdx.x * blockDim.x + threadIdx.x;
    if (gtid < BATCH * DIM) g_q2c[gtid] = 0.f;

    int warp = gtid >> 5;
    int lane = threadIdx.x & 31;
    const int NC = BATCH * LC;
    if (warp < NC) {
        const float* src = c + (size_t)warp * DIM;
        float s = 0.f;
#pragma unroll
        for (int i = 0; i < 8; i++) {
            int k = (lane + i * 32) * 4;
            float4 v = *(const float4*)(src + k);
            float4 p = *(const float4*)(pc + k);
            s += v.x * p.x + v.y * p.y + v.z * p.z + v.w * p.w;
        }
#pragma unroll
        for (int o = 16; o; o >>= 1) s += __shfl_xor_sync(0xffffffffu, s, o);
        if (lane == 0) g_s0[warp] = s;
    } else if (warp < NC + BATCH * LQ) {
        int r = warp - NC;
        const float* src = q + (size_t)r * DIM;
        float* dst = g_qs + (size_t)r * DIM;
        float s = 0.f;
#pragma unroll
        for (int i = 0; i < 8; i++) {
            int k = (lane + i * 32) * 4;
            float4 v  = *(const float4*)(src + k);
            float4 pp = *(const float4*)(pq + k);
            s += v.x * pp.x + v.y * pp.y + v.z * pp.z + v.w * pp.w;
            float4 pv = *(const float4*)(pcq + k);
            float4 o = {v.x * pv.x, v.y * pv.y, v.z * pv.z, v.w * pv.w};
            *(float4*)(dst + k) = o;
        }
#pragma unroll
        for (int o = 16; o; o >>= 1) s += __shfl_xor_sync(0xffffffffu, s, o);
        if (lane == 0) g_s1[r] = s;
    }
}

// ---------------- K1: sim GEMM: sim = c @ qs^T + s0 + s1 ; rowmax -----------
// tile 64x64, 128 threads, micro 8(m)x4(n), f32x2 over K pairs,
// K-major smem, cp.async double buffer.
#define KT 32
#define AW 36   // padded row width (144 B, 16B aligned; banks shift 4/row)
__global__ void __launch_bounds__(128, 2)
k_sim(const float* __restrict__ c) {
    __shared__ __align__(16) float sm[2 * 64 * AW * 2];   // As | Bs (36 KB)
    float (*As)[64][AW] = (float(*)[64][AW])sm;
    float (*Bs)[64][AW] = (float(*)[64][AW])(sm + 2 * 64 * AW);
    float (*sim_s)[68] = (float(*)[68])sm;                // epilogue alias

    int b = blockIdx.y, cm = blockIdx.x;
    int tl = threadIdx.x;
    int tx = tl & 15;          // n-thread
    int ty = tl >> 4;          // m-thread (0..7)

    const float* cA = c + ((size_t)b * LC + cm * 64) * DIM;
    const float* cB = g_qs + (size_t)b * LQ * DIM;

    int lrow = tl >> 1;                 // 0..63
    int lhalf = (tl & 1) * 16;          // k-offset within slice
    unsigned sa0 = (unsigned)__cvta_generic_to_shared(&As[0][lrow][lhalf]);
    unsigned sb0 = (unsigned)__cvta_generic_to_shared(&Bs[0][lrow][lhalf]);
    const unsigned PPSTRIDE = 64 * AW * 4;
    const float* gA = cA + (size_t)lrow * DIM + lhalf;
    const float* gB = cB + (size_t)lrow * DIM + lhalf;

    u64 acc[8][4];
#pragma unroll
    for (int i = 0; i < 8; i++)
#pragma unroll
        for (int j = 0; j < 4; j++) acc[i][j] = 0ull;

    // prefetch slice 0 into buffer 0
#pragma unroll
    for (int j = 0; j < 4; j++) {
        cp16(sa0 + j * 16, gA + j * 4);
        cp16(sb0 + j * 16, gB + j * 4);
    }
    CP_COMMIT();

    for (int it = 0; it < DIM / KT; it++) {
        int nit = (it + 1 < DIM / KT) ? it + 1 : it;   // dummy refetch on last
        int npp = (it + 1) & 1;
#pragma unroll
        for (int j = 0; j < 4; j++) {
            cp16(sa0 + npp * PPSTRIDE + j * 16, gA + nit * KT + j * 4);
            cp16(sb0 + npp * PPSTRIDE + j * 16, gB + nit * KT + j * 4);
        }
        CP_COMMIT();
        CP_WAIT1();
        __syncthreads();

        int pp = it & 1;
#pragma unroll
        for (int kk2 = 0; kk2 < KT / 2; kk2++) {
            u64 am[8], bn[4];
#pragma unroll
            for (int i = 0; i < 8; i++)
                am[i] = *(const u64*)&As[pp][ty + 8 * i][2 * kk2];
#pragma unroll
            for (int j = 0; j < 4; j++)
                bn[j] = *(const u64*)&Bs[pp][tx + 16 * j][2 * kk2];
#pragma unroll
            for (int i = 0; i < 8; i++)
#pragma unroll
                for (int j = 0; j < 4; j++)
                    acc[i][j] = ffma2(am[i], bn[j], acc[i][j]);
        }
        __syncthreads();
    }

    // epilogue: add s0 + s1, rowmax over 16 tx lanes, stage + coalesced write
    float s1v[4];
#pragma unroll
    for (int j = 0; j < 4; j++) s1v[j] = g_s1[b * LQ + tx + 16 * j];
#pragma unroll
    for (int i = 0; i < 8; i++) {
        int m = ty + 8 * i;
        float s0v = g_s0[b * LC + cm * 64 + m];
        float rm = -3.4e38f;
        float vals[4];
#pragma unroll
        for (int j = 0; j < 4; j++) {
            vals[j] = pairsum(acc[i][j]) + s0v + s1v[j];
            rm = fmaxf(rm, vals[j]);
        }
#pragma unroll
        for (int o = 8; o; o >>= 1) rm = fmaxf(rm, __shfl_xor_sync(0xffffffffu, rm, o));
#pragma unroll
        for (int j = 0; j < 4; j++) sim_s[m][tx + 16 * j] = vals[j];
        if (tx == 0) g_m[b * LC + cm * 64 + m] = rm;
    }
    __syncthreads();

    int wrow = tl >> 1;
    int wcol = (tl & 1) * 32;
    float* gdst = &g_sim[((size_t)b * LC + cm * 64 + wrow) * LQ + wcol];
#pragma unroll
    for (int j = 0; j < 8; j++)
        *(float4*)(gdst + 4 * j) = *(const float4*)&sim_s[wrow][wcol + 4 * j];
}

// ---------------- K2: q2c[b,:] = softmax_c(m) @ c[b] ------------------------
__global__ void k_q2c(const float* __restrict__ c) {
    __shared__ float wm[LC];
    __shared__ float red[256];
    int b = blockIdx.y, cb = blockIdx.x;
    int t = threadIdx.x;
    float v0 = g_m[b * LC + t];
    float v1 = g_m[b * LC + 256 + t];
    red[t] = fmaxf(v0, v1);
    __syncthreads();
#pragma unroll
    for (int s = 128; s > 0; s >>= 1) {
        if (t < s) red[t] = fmaxf(red[t], red[t + s]);
        __syncthreads();
    }
    float mx = red[0];
    __syncthreads();
    float e0 = expf(v0 - mx), e1 = expf(v1 - mx);
    wm[t] = e0;
    wm[t + 256] = e1;
    red[t] = e0 + e1;
    __syncthreads();
#pragma unroll
    for (int s = 128; s > 0; s >>= 1) {
        if (t < s) red[t] += red[t + s];
        __syncthreads();
    }
    float inv = 1.f / red[0];
    __syncthreads();

    float4 acc = {0.f, 0.f, 0.f, 0.f};
    const float* cb0 = c + ((size_t)b * LC + cb * 32) * DIM + (t << 2);
#pragma unroll 8
    for (int cr = 0; cr < 32; cr++) {
        float w = wm[cb * 32 + cr] * inv;
        float4 cv = *(const float4*)(cb0 + (size_t)cr * DIM);
        acc.x = fmaf(w, cv.x, acc.x);
        acc.y = fmaf(w, cv.y, acc.y);
        acc.z = fmaf(w, cv.z, acc.z);
        acc.w = fmaf(w, cv.w, acc.w);
    }
    float* dst = g_q2c + b * DIM + (t << 2);
    atomicAdd(dst + 0, acc.x);
    atomicAdd(dst + 1, acc.y);
    atomicAdd(dst + 2, acc.z);
    atomicAdd(dst + 3, acc.w);
}

// ---------------- K3: softmax rows, c2q = a @ q (row-paired f32x2), output --
#define RT 64
#define DC 128
__global__ void k_out(const float* __restrict__ c, const float* __restrict__ q,
                      float* __restrict__ out) {
    __shared__ float a_sT[LQ][RT];                 // [qq][r] 16 KB
    __shared__ __align__(16) float q_s[LQ][DC];    // 32 KB (48 KB total)
    int b = blockIdx.y, ct = blockIdx.x;
    int t = threadIdx.x;
    int warp = t >> 5, lane = t & 31;

    // row softmax using stored rowmax; transposed store
#pragma unroll
    for (int i = 0; i < 8; i++) {
        int r = warp * 8 + i;
        int row = ct * RT + r;
        size_t sbase = ((size_t)b * LC + row) * LQ;
        float m = g_m[b * LC + row];
        float v0 = expf(g_sim[sbase + lane] - m);
        float v1 = expf(g_sim[sbase + lane + 32] - m);
        float s = v0 + v1;
#pragma unroll
        for (int o = 16; o; o >>= 1) s += __shfl_xor_sync(0xffffffffu, s, o);
        float inv = 1.f / s;
        a_sT[lane][r] = v0 * inv;
        a_sT[lane + 32][r] = v1 * inv;
    }
    __syncthreads();

    const float* qb = q + (size_t)b * LQ * DIM;
    int rbase = warp * 8;        // 8 rows = 4 row-pairs per warp

    for (int dc = 0; dc < DIM; dc += DC) {
#pragma unroll
        for (int i = 0; i < 8; i++) {
            int idx = t + i * 256;
            int qr = idx >> 5;
            int qc = (idx & 31) << 2;
            *(float4*)&q_s[qr][qc] = *(const float4*)(qb + (size_t)qr * DIM + dc + qc);
        }
        __syncthreads();

        // acc[p][d]: row-pair p (rows rbase+2p, +2p+1), d one of 4 owned cols
        u64 acc[4][4];
#pragma unroll
        for (int p = 0; p < 4; p++)
#pragma unroll
            for (int d = 0; d < 4; d++) acc[p][d] = 0ull;

#pragma unroll 8
        for (int qq = 0; qq < LQ; qq++) {
            float4 qv = *(const float4*)&q_s[qq][lane << 2];
            u64 qd[4] = {pack2(qv.x, qv.x), pack2(qv.y, qv.y),
                         pack2(qv.z, qv.z), pack2(qv.w, qv.w)};
            u64 ar[4];
#pragma unroll
            for (int p = 0; p < 4; p++)
                ar[p] = *(const u64*)&a_sT[qq][rbase + 2 * p];
#pragma unroll
            for (int p = 0; p < 4; p++)
#pragma unroll
                for (int d = 0; d < 4; d++)
                    acc[p][d] = ffma2(ar[p], qd[d], acc[p][d]);
        }

        int d0 = dc + (lane << 2);
        float4 qc4 = *(const float4*)(g_q2c + b * DIM + d0);
#pragma unroll
        for (int p = 0; p < 4; p++) {
            float2 u0 = unpack2(acc[p][0]);
            float2 u1 = unpack2(acc[p][1]);
            float2 u2 = unpack2(acc[p][2]);
            float2 u3 = unpack2(acc[p][3]);
            float4 arow[2] = {{u0.x, u1.x, u2.x, u3.x}, {u0.y, u1.y, u2.y, u3.y}};
#pragma unroll
            for (int e = 0; e < 2; e++) {
                int row = ct * RT + rbase + 2 * p + e;
                float4 a4 = arow[e];
                float4 cv = *(const float4*)(c + ((size_t)b * LC + row) * DIM + d0);
                float* ob = out + ((size_t)b * LC + row) * (4 * DIM) + d0;
                *(float4*)(ob) = cv;
                *(float4*)(ob + DIM) = a4;
                float4 t2 = {cv.x * qc4.x, cv.y * qc4.y, cv.z * qc4.z, cv.w * qc4.w};
                *(float4*)(ob + 2 * DIM) = t2;
                float4 t3 = {cv.x * a4.x, cv.y * a4.y, cv.z * a4.z, cv.w * a4.w};
                *(float4*)(ob + 3 * DIM) = t3;
            }
        }
        __syncthreads();
    }
}

// ---------------- launch -----------------------------------------------------
extern "C" void kernel_launch(void* const* d_in, const int* in_sizes, int n_in,
                              void* d_out, int out_size) {
    const float* c   = (const float*)d_in[0];
    const float* q   = (const float*)d_in[1];
    const float* pc  = (const float*)d_in[2];
    const float* pq  = (const float*)d_in[3];
    const float* pcq = (const float*)d_in[4];
    float* out = (float*)d_out;
    (void)in_sizes; (void)n_in; (void)out_size;

    k_pre<<<BATCH * (LC + LQ) * 32 / 256, 256>>>(c, q, pc, pq, pcq);
    k_sim<<<dim3(LC / 64, BATCH), 128>>>(c);
    k_q2c<<<dim3(16, BATCH), 256>>>(c);
    k_out<<<dim3(LC / RT, BATCH), 256>>>(c, q, out);
}

// round 5
// speedup vs baseline: 1.7713x; 1.0092x over previous
#include <cuda_runtime.h>

#define BATCH 32
#define LC 512
#define LQ 64
#define DIM 1024

typedef unsigned long long u64;

__device__ __forceinline__ u64 ffma2(u64 a, u64 b, u64 c) {
    u64 d;
    asm("fma.rn.f32x2 %0, %1, %2, %3;" : "=l"(d) : "l"(a), "l"(b), "l"(c));
    return d;
}
__device__ __forceinline__ u64 pack2(float x, float y) {
    u64 d;
    asm("mov.b64 %0, {%1, %2};" : "=l"(d) : "f"(x), "f"(y));
    return d;
}
__device__ __forceinline__ float2 unpack2(u64 v) {
    float2 r;
    asm("mov.b64 {%0, %1}, %2;" : "=f"(r.x), "=f"(r.y) : "l"(v));
    return r;
}
__device__ __forceinline__ float pairsum(u64 v) {
    float2 r = unpack2(v);
    return r.x + r.y;
}
__device__ __forceinline__ void cp16(unsigned saddr, const void* gaddr) {
    asm volatile("cp.async.cg.shared.global [%0], [%1], 16;"
                 :: "r"(saddr), "l"(gaddr) : "memory");
}
#define CP_COMMIT() asm volatile("cp.async.commit_group;" ::: "memory")
#define CP_WAIT1()  asm volatile("cp.async.wait_group 1;" ::: "memory")

// ---------------- scratch -----------------------------------------------------
__device__ float g_s0[BATCH * LC];          // c @ proj_c
__device__ float g_s1[BATCH * LQ];          // q @ proj_q
__device__ float g_qs[BATCH * LQ * DIM];    // q * proj_cq (8 MiB)
__device__ float g_sim[BATCH * LC * LQ];    // similarity matrix (4 MiB)
__device__ float g_m[BATCH * LC];           // rowmax of sim over q
__device__ float g_q2c[BATCH * DIM];        // query-to-context vector

// ---------------- K0: projections + scaled q + zero q2c ---------------------
__global__ void k_pre(const float* __restrict__ c, const float* __restrict__ q,
                      const float* __restrict__ pc, const float* __restrict__ pq,
                      const float* __restrict__ pcq) {
    int gtid = blockIdx.x * blockDim.x + threadIdx.x;
    if (gtid < BATCH * DIM) g_q2c[gtid] = 0.f;

    int warp = gtid >> 5;
    int lane = threadIdx.x & 31;
    const int NC = BATCH * LC;
    if (warp < NC) {
        const float* src = c + (size_t)warp * DIM;
        float s = 0.f;
#pragma unroll
        for (int i = 0; i < 8; i++) {
            int k = (lane + i * 32) * 4;
            float4 v = *(const float4*)(src + k);
            float4 p = *(const float4*)(pc + k);
            s += v.x * p.x + v.y * p.y + v.z * p.z + v.w * p.w;
        }
#pragma unroll
        for (int o = 16; o; o >>= 1) s += __shfl_xor_sync(0xffffffffu, s, o);
        if (lane == 0) g_s0[warp] = s;
    } else if (warp < NC + BATCH * LQ) {
        int r = warp - NC;
        const float* src = q + (size_t)r * DIM;
        float* dst = g_qs + (size_t)r * DIM;
        float s = 0.f;
#pragma unroll
        for (int i = 0; i < 8; i++) {
            int k = (lane + i * 32) * 4;
            float4 v  = *(const float4*)(src + k);
            float4 pp = *(const float4*)(pq + k);
            s += v.x * pp.x + v.y * pp.y + v.z * pp.z + v.w * pp.w;
            float4 pv = *(const float4*)(pcq + k);
            float4 o = {v.x * pv.x, v.y * pv.y, v.z * pv.z, v.w * pv.w};
            *(float4*)(dst + k) = o;
        }
#pragma unroll
        for (int o = 16; o; o >>= 1) s += __shfl_xor_sync(0xffffffffu, s, o);
        if (lane == 0) g_s1[r] = s;
    }
}

// ---------------- K1: sim GEMM: sim = c @ qs^T + s0 + s1 ; rowmax -----------
// tile 32(m)x64(n), 128 threads, micro 4x4 f32x2 K-pairs, cp.async dbl-buffer
// grid (16, 32) = 512 blocks for occupancy.
#define KT 32
#define AW 36
__global__ void __launch_bounds__(128, 6)
k_sim(const float* __restrict__ c) {
    __shared__ __align__(16) float As[2][32][AW];   // 9 KB
    __shared__ __align__(16) float Bs[2][64][AW];   // 18 KB

    int b = blockIdx.y, cm = blockIdx.x;
    int tl = threadIdx.x;
    int tx = tl & 15;          // n-thread (16 x 4 = 64)
    int ty = tl >> 4;          // m-thread (8 x 4 = 32)

    const float* cA = c + ((size_t)b * LC + cm * 32) * DIM;
    const float* cB = g_qs + (size_t)b * LQ * DIM;

    int lrow = tl >> 3;             // 0..15
    int lkp = (tl & 7) * 4;         // 0..28
    const float* gA0 = cA + (size_t)lrow * DIM + lkp;
    const float* gB0 = cB + (size_t)lrow * DIM + lkp;
    unsigned saA = (unsigned)__cvta_generic_to_shared(&As[0][lrow][lkp]);
    unsigned saB = (unsigned)__cvta_generic_to_shared(&Bs[0][lrow][lkp]);
    const unsigned SA = 32 * AW * 4;    // As buffer stride
    const unsigned SB = 64 * AW * 4;    // Bs buffer stride
    const unsigned R16A = 16 * AW * 4;  // 16 rows in As
    const unsigned R16B = 16 * AW * 4;

    u64 acc[4][4];
#pragma unroll
    for (int i = 0; i < 4; i++)
#pragma unroll
        for (int j = 0; j < 4; j++) acc[i][j] = 0ull;

    // prefetch slice 0 -> buffer 0
    cp16(saA, gA0);
    cp16(saA + R16A, gA0 + 16 * DIM);
#pragma unroll
    for (int i = 0; i < 4; i++)
        cp16(saB + i * R16B, gB0 + (size_t)(16 * i) * DIM);
    CP_COMMIT();

    for (int it = 0; it < DIM / KT; it++) {
        int nit = (it + 1 < DIM / KT) ? it + 1 : it;
        unsigned nb = ((it + 1) & 1);
        cp16(saA + nb * SA, gA0 + nit * KT);
        cp16(saA + nb * SA + R16A, gA0 + 16 * DIM + nit * KT);
#pragma unroll
        for (int i = 0; i < 4; i++)
            cp16(saB + nb * SB + i * R16B, gB0 + (size_t)(16 * i) * DIM + nit * KT);
        CP_COMMIT();
        CP_WAIT1();
        __syncthreads();

        int pp = it & 1;
#pragma unroll
        for (int kk2 = 0; kk2 < KT / 2; kk2++) {
            u64 am[4], bn[4];
#pragma unroll
            for (int i = 0; i < 4; i++)
                am[i] = *(const u64*)&As[pp][ty + 8 * i][2 * kk2];
#pragma unroll
            for (int j = 0; j < 4; j++)
                bn[j] = *(const u64*)&Bs[pp][tx + 16 * j][2 * kk2];
#pragma unroll
            for (int i = 0; i < 4; i++)
#pragma unroll
                for (int j = 0; j < 4; j++)
                    acc[i][j] = ffma2(am[i], bn[j], acc[i][j]);
        }
        __syncthreads();
    }

    // epilogue: add s0 + s1, rowmax over 16 tx lanes, stage, coalesced write
    float (*sim_s)[68] = (float(*)[68])&As[0][0][0];   // 32x68 fits in As
    float s1v[4];
#pragma unroll
    for (int j = 0; j < 4; j++) s1v[j] = g_s1[b * LQ + tx + 16 * j];
#pragma unroll
    for (int i = 0; i < 4; i++) {
        int m = ty + 8 * i;
        float s0v = g_s0[b * LC + cm * 32 + m];
        float rm = -3.4e38f;
        float vals[4];
#pragma unroll
        for (int j = 0; j < 4; j++) {
            vals[j] = pairsum(acc[i][j]) + s0v + s1v[j];
            rm = fmaxf(rm, vals[j]);
        }
#pragma unroll
        for (int o = 8; o; o >>= 1) rm = fmaxf(rm, __shfl_xor_sync(0xffffffffu, rm, o));
#pragma unroll
        for (int j = 0; j < 4; j++) sim_s[m][tx + 16 * j] = vals[j];
        if (tx == 0) g_m[b * LC + cm * 32 + m] = rm;
    }
    __syncthreads();

#pragma unroll
    for (int i = 0; i < 4; i++) {
        int idx = tl + 128 * i;           // 0..511 float4s
        int wrow = idx >> 4;
        int wcol = (idx & 15) * 4;
        *(float4*)&g_sim[((size_t)b * LC + cm * 32 + wrow) * LQ + wcol] =
            *(const float4*)&sim_s[wrow][wcol];
    }
}

// ---------------- K2: q2c[b,:] = softmax_c(m) @ c[b] ------------------------
// grid (32, B): 16 c-rows per block
__global__ void k_q2c(const float* __restrict__ c) {
    __shared__ float wm[LC];
    __shared__ float red[256];
    int b = blockIdx.y, cb = blockIdx.x;
    int t = threadIdx.x;
    float v0 = g_m[b * LC + t];
    float v1 = g_m[b * LC + 256 + t];
    red[t] = fmaxf(v0, v1);
    __syncthreads();
#pragma unroll
    for (int s = 128; s > 0; s >>= 1) {
        if (t < s) red[t] = fmaxf(red[t], red[t + s]);
        __syncthreads();
    }
    float mx = red[0];
    __syncthreads();
    float e0 = expf(v0 - mx), e1 = expf(v1 - mx);
    wm[t] = e0;
    wm[t + 256] = e1;
    red[t] = e0 + e1;
    __syncthreads();
#pragma unroll
    for (int s = 128; s > 0; s >>= 1) {
        if (t < s) red[t] += red[t + s];
        __syncthreads();
    }
    float inv = 1.f / red[0];
    __syncthreads();

    float4 acc = {0.f, 0.f, 0.f, 0.f};
    const float* cb0 = c + ((size_t)b * LC + cb * 16) * DIM + (t << 2);
#pragma unroll
    for (int cr = 0; cr < 16; cr++) {
        float w = wm[cb * 16 + cr] * inv;
        float4 cv = *(const float4*)(cb0 + (size_t)cr * DIM);
        acc.x = fmaf(w, cv.x, acc.x);
        acc.y = fmaf(w, cv.y, acc.y);
        acc.z = fmaf(w, cv.z, acc.z);
        acc.w = fmaf(w, cv.w, acc.w);
    }
    float* dst = g_q2c + b * DIM + (t << 2);
    atomicAdd(dst + 0, acc.x);
    atomicAdd(dst + 1, acc.y);
    atomicAdd(dst + 2, acc.z);
    atomicAdd(dst + 3, acc.w);
}

// ---------------- K3: softmax rows, c2q = a @ q (row-paired f32x2), output --
// swizzled a_sT to kill transposed-store bank conflicts; 3 CTAs/SM
#define RT 64
#define DC 128
#define SWZ(qq, r) ((r) ^ (((qq) & 15) << 1))
__global__ void __launch_bounds__(256, 3)
k_out(const float* __restrict__ c, const float* __restrict__ q,
      float* __restrict__ out) {
    __shared__ float a_sT[LQ][RT];                 // swizzled [qq][r'] 16 KB
    __shared__ __align__(16) float q_s[LQ][DC];    // 32 KB (48 KB total)
    int b = blockIdx.y, ct = blockIdx.x;
    int t = threadIdx.x;
    int warp = t >> 5, lane = t & 31;

    // row softmax using stored rowmax; swizzled transposed store (2-way max)
#pragma unroll
    for (int i = 0; i < 8; i++) {
        int r = warp * 8 + i;
        int row = ct * RT + r;
        size_t sbase = ((size_t)b * LC + row) * LQ;
        float m = g_m[b * LC + row];
        float v0 = expf(g_sim[sbase + lane] - m);
        float v1 = expf(g_sim[sbase + lane + 32] - m);
        float s = v0 + v1;
#pragma unroll
        for (int o = 16; o; o >>= 1) s += __shfl_xor_sync(0xffffffffu, s, o);
        float inv = 1.f / s;
        a_sT[lane][SWZ(lane, r)] = v0 * inv;
        a_sT[lane + 32][SWZ(lane, r)] = v1 * inv;
    }
    __syncthreads();

    const float* qb = q + (size_t)b * LQ * DIM;
    int rbase = warp * 8;        // 8 rows = 4 row-pairs per warp

    for (int dc = 0; dc < DIM; dc += DC) {
#pragma unroll
        for (int i = 0; i < 8; i++) {
            int idx = t + i * 256;
            int qr = idx >> 5;
            int qc = (idx & 31) << 2;
            *(float4*)&q_s[qr][qc] = *(const float4*)(qb + (size_t)qr * DIM + dc + qc);
        }
        __syncthreads();

        u64 acc[4][4];
#pragma unroll
        for (int p = 0; p < 4; p++)
#pragma unroll
            for (int d = 0; d < 4; d++) acc[p][d] = 0ull;

#pragma unroll 8
        for (int qq = 0; qq < LQ; qq++) {
            float4 qv = *(const float4*)&q_s[qq][lane << 2];
            u64 qd[4] = {pack2(qv.x, qv.x), pack2(qv.y, qv.y),
                         pack2(qv.z, qv.z), pack2(qv.w, qv.w)};
            u64 ar[4];
#pragma unroll
            for (int p = 0; p < 4; p++)
                ar[p] = *(const u64*)&a_sT[qq][SWZ(qq, rbase + 2 * p)];
#pragma unroll
            for (int p = 0; p < 4; p++)
#pragma unroll
                for (int d = 0; d < 4; d++)
                    acc[p][d] = ffma2(ar[p], qd[d], acc[p][d]);
        }

        int d0 = dc + (lane << 2);
        float4 qc4 = *(const float4*)(g_q2c + b * DIM + d0);
#pragma unroll
        for (int p = 0; p < 4; p++) {
            float2 u0 = unpack2(acc[p][0]);
            float2 u1 = unpack2(acc[p][1]);
            float2 u2 = unpack2(acc[p][2]);
            float2 u3 = unpack2(acc[p][3]);
            float4 arow[2] = {{u0.x, u1.x, u2.x, u3.x}, {u0.y, u1.y, u2.y, u3.y}};
#pragma unroll
            for (int e = 0; e < 2; e++) {
                int row = ct * RT + rbase + 2 * p + e;
                float4 a4 = arow[e];
                float4 cv = *(const float4*)(c + ((size_t)b * LC + row) * DIM + d0);
                float* ob = out + ((size_t)b * LC + row) * (4 * DIM) + d0;
                *(float4*)(ob) = cv;
                *(float4*)(ob + DIM) = a4;
                float4 t2 = {cv.x * qc4.x, cv.y * qc4.y, cv.z * qc4.z, cv.w * qc4.w};
                *(float4*)(ob + 2 * DIM) = t2;
                float4 t3 = {cv.x * a4.x, cv.y * a4.y, cv.z * a4.z, cv.w * a4.w};
                *(float4*)(ob + 3 * DIM) = t3;
            }
        }
        __syncthreads();
    }
}

// ---------------- launch -----------------------------------------------------
extern "C" void kernel_launch(void* const* d_in, const int* in_sizes, int n_in,
                              void* d_out, int out_size) {
    const float* c   = (const float*)d_in[0];
    const float* q   = (const float*)d_in[1];
    const float* pc  = (const float*)d_in[2];
    const float* pq  = (const float*)d_in[3];
    const float* pcq = (const float*)d_in[4];
    float* out = (float*)d_out;
    (void)in_sizes; (void)n_in; (void)out_size;

    k_pre<<<BATCH * (LC + LQ) * 32 / 256, 256>>>(c, q, pc, pq, pcq);
    k_sim<<<dim3(LC / 32, BATCH), 128>>>(c);
    k_q2c<<<dim3(32, BATCH), 256>>>(c);
    k_out<<<dim3(LC / RT, BATCH), 256>>>(c, q, out);
}